// round 15
// baseline (speedup 1.0000x reference)
#include <cuda_runtime.h>
#include <cuda_bf16.h>
#include <cuda_fp16.h>
#include <cstdint>

#define BB 32
#define TT 512
#define DD 768
#define HH 512
#define CC 7
#define K2 2048
#define N4H 2048
#define BH 16            // batch half
#define DOMS 4           // (dir x batch-half) domains

// ---------------- device state ----------------
__device__ __half g_ench[BB*TT*HH];        // enc_proj fp16 (16.7MB)
__device__ __half g_xh[BB*TT*DD];          // fp16 x (25MB)
__device__ uint2 g_WcatPh[2*128*256*32];   // frag-packed fp16 weights (16.7MB)
__device__ float g_bcat[2*N4H];
__device__ float g_WdecT[HH*HH];
__device__ float g_h[DOMS*BH*HH];
__device__ float g_c[DOMS*BH*HH];
__device__ float g_decp[8*DOMS*BH*HH];     // [kc8][dom][b16][n]
__device__ float g_mp[2*8*DOMS*BH];        // ping-pong maxes [par][tp8][dom][b]
__device__ float g_zp[8*DOMS*BH];          // partial Z [tp8][dom][b]
__device__ float g_ctxp[8*DOMS*BH*DD];     // unnormalized ctx partials
__device__ float g_gpart[DOMS*8*BH*N4H];   // [dom][kc8][b16][jj] (4.2MB)
__device__ float g_hs[2*TT*BB*HH];
__device__ unsigned g_arr[DOMS*32];        // per-domain counters, 128B apart

// ---------------- helpers ----------------
__device__ __forceinline__ float fast_tanh(float x){
    float y; asm("tanh.approx.f32 %0, %1;" : "=f"(y) : "f"(x)); return y;
}
__device__ __forceinline__ float tanh_acc(float x){
    float e = __expf(x + x);
    return 1.0f - __fdividef(2.0f, e + 1.0f);
}
__device__ __forceinline__ float sigm(float x){ return 1.0f/(1.0f+__expf(-x)); }
__device__ __forceinline__ float warpMax(float v){
    #pragma unroll
    for(int o=16;o;o>>=1) v = fmaxf(v, __shfl_xor_sync(0xffffffffu, v, o));
    return v;
}
__device__ __forceinline__ float warpSum(float v){
    #pragma unroll
    for(int o=16;o;o>>=1) v += __shfl_xor_sync(0xffffffffu, v, o);
    return v;
}
__device__ __forceinline__ void mma_f16(float* c, const uint32_t* a, uint32_t b0, uint32_t b1){
    asm volatile("mma.sync.aligned.m16n8k16.row.col.f32.f16.f16.f32 "
                 "{%0,%1,%2,%3}, {%4,%5,%6,%7}, {%8,%9}, {%0,%1,%2,%3};"
                 : "+f"(c[0]), "+f"(c[1]), "+f"(c[2]), "+f"(c[3])
                 : "r"(a[0]), "r"(a[1]), "r"(a[2]), "r"(a[3]), "r"(b0), "r"(b1));
}
__device__ __forceinline__ void hbar(int id){
    asm volatile("bar.sync %0, %1;" :: "r"(id), "r"(256) : "memory");
}
__device__ __forceinline__ void gbarh(int id, unsigned* ctr, unsigned target, int htid){
    hbar(id);
    if(htid == 0){
        asm volatile("red.release.gpu.global.add.u32 [%0], %1;"
                     :: "l"(ctr), "r"(1u) : "memory");
        unsigned vv;
        #pragma unroll 1
        do { asm volatile("ld.acquire.gpu.u32 %0, [%1];" : "=r"(vv) : "l"(ctr)); } while(vv < target);
    }
    hbar(id);
}

// ---------------- init ----------------
__global__ void k_init(const float* __restrict__ b_dec){
    int i = blockIdx.x*blockDim.x + threadIdx.x;
    if(i < DOMS*32) g_arr[i] = 0u;
    if(i < 2*8*DOMS*BH) g_mp[i] = 0.f;
    if(i < 8*DOMS*BH) g_zp[i] = 1.f;
    if(i < DOMS*BH*HH){ g_h[i]=0.f; g_c[i]=0.f; }
    if(i < 8*DOMS*BH*HH){
        int kc = i >> 15;                       // DOMS*BH*HH = 32768
        g_decp[i] = (kc==0) ? b_dec[i & (HH-1)] : 0.f;
    }
}

// ---------------- prep ----------------
__global__ void k_prep(const float* __restrict__ Wf_ih, const float* __restrict__ Wf_hh,
                       const float* __restrict__ bf,
                       const float* __restrict__ Wb_ih, const float* __restrict__ Wb_hh,
                       const float* __restrict__ bb,
                       const float* __restrict__ W_dec,
                       const float* __restrict__ x){
    int tid0 = blockIdx.x*blockDim.x + threadIdx.x;
    int stride = gridDim.x*blockDim.x;
    for(int i = tid0; i < 2*128*256*32; i += stride){
        int lane = i & 31;
        int n8 = (i>>5) & 255;
        int k16 = (i>>13) & 127;
        int dir = (i>>20) & 1;
        int gq = lane>>2, tq = lane&3;
        int n = n8*8 + gq;
        int j = ((n&3)<<9) + (n>>2);
        const float* Wih = dir ? Wb_ih : Wf_ih;
        const float* Whh = dir ? Wb_hh : Wf_hh;
        int ka = k16*16 + 2*tq;
        int kb = ka + 8;
        float wa0 = (ka   < 1536) ? Wih[j*1536 + ka]   : Whh[j*512 + (ka-1536)];
        float wa1 = (ka+1 < 1536) ? Wih[j*1536 + ka+1] : Whh[j*512 + (ka+1-1536)];
        float wb0 = (kb   < 1536) ? Wih[j*1536 + kb]   : Whh[j*512 + (kb-1536)];
        float wb1 = (kb+1 < 1536) ? Wih[j*1536 + kb+1] : Whh[j*512 + (kb+1-1536)];
        __half2 h0 = __floats2half2_rn(wa0, wa1);
        __half2 h1 = __floats2half2_rn(wb0, wb1);
        g_WcatPh[i] = make_uint2(*(uint32_t*)&h0, *(uint32_t*)&h1);
    }
    for(int i = tid0; i < BB*TT*DD; i += stride){
        g_xh[i] = __float2half(x[i]);
    }
    if(tid0 < 2*N4H){
        int jj = tid0 & (N4H-1); int dir = tid0 >> 11;
        int j = ((jj&3)<<9) + (jj>>2);
        g_bcat[tid0] = dir ? bb[j] : bf[j];
    }
    if(tid0 < HH*HH){
        int n = tid0 & (HH-1); int k = tid0 >> 9;
        g_WdecT[k*HH + n] = W_dec[n*HH + k];
    }
}

// ---------------- enc_proj GEMM (fp16 out) ----------------
__global__ void k_enc_gemm(const float* __restrict__ A, const float* __restrict__ Bm,
                           const float* __restrict__ bias){
    __shared__ float As[16][68];
    __shared__ float Bs[16][68];
    const int Kk = DD, Nn = HH;
    int n0 = blockIdx.x*64, m0 = blockIdx.y*64;
    int tid = threadIdx.x;
    int tm = tid>>4, tn = tid&15;
    float acc[4][4];
    #pragma unroll
    for(int i=0;i<4;i++)
        #pragma unroll
        for(int j=0;j<4;j++) acc[i][j] = bias[n0 + tn*4 + j];

    int lrow = tid>>2, lkq = (tid&3)*4;
    for(int k0=0;k0<Kk;k0+=16){
        float4 av = *(const float4*)&A[(long)(m0+lrow)*Kk + k0 + lkq];
        float4 bv = *(const float4*)&Bm[(long)(n0+lrow)*Kk + k0 + lkq];
        __syncthreads();
        As[lkq+0][lrow]=av.x; As[lkq+1][lrow]=av.y; As[lkq+2][lrow]=av.z; As[lkq+3][lrow]=av.w;
        Bs[lkq+0][lrow]=bv.x; Bs[lkq+1][lrow]=bv.y; Bs[lkq+2][lrow]=bv.z; Bs[lkq+3][lrow]=bv.w;
        __syncthreads();
        #pragma unroll
        for(int kk=0;kk<16;kk++){
            float4 a4 = *(const float4*)&As[kk][tm*4];
            float4 b4 = *(const float4*)&Bs[kk][tn*4];
            float aa[4] = {a4.x,a4.y,a4.z,a4.w};
            float bb4[4] = {b4.x,b4.y,b4.z,b4.w};
            #pragma unroll
            for(int i=0;i<4;i++)
                #pragma unroll
                for(int j=0;j<4;j++) acc[i][j] += aa[i]*bb4[j];
        }
    }
    #pragma unroll
    for(int i=0;i<4;i++)
        #pragma unroll
        for(int j=0;j<4;j++)
            g_ench[(long)(m0+tm*4+i)*Nn + n0 + tn*4 + j] = __float2half(acc[i][j]);
}

// ---------------- persistent kernel: 4 domains, 2 per block (warp-specialized) --
union SH {
    struct { float d0[HH], vs[HH], sw0[64], red0[2], red1[2]; } a;   // 4.3KB
    struct { uint32_t Ap[2048]; float zinv[BH]; } c;                 // 8.3KB
    struct { float Hs[BH][64]; float Ws[64][32]; } e;                // 12KB
};

__global__ void __launch_bounds__(512, 2)
k_persist(const float* __restrict__ x, const float* __restrict__ v,
          const float* __restrict__ b_dec, int NSM){
    __shared__ SH sh[2];
    const int tid = threadIdx.x;
    const int hf = tid >> 8;                 // half: batch group
    const int htid = tid & 255;
    const int lane = htid & 31, warp = htid >> 5;
    const int dir = (blockIdx.x >= NSM) ? 1 : 0;
    const int dbid = blockIdx.x - dir*NSM;
    const int dom = dir*2 + hf;
    const int barid = hf + 1;
    unsigned* ctr = &g_arr[dom*32];
    SH& S = sh[hf];
    unsigned bt = (unsigned)NSM;

    for(int s=0; s<TT; s++){
        const int t_cur = dir ? (TT-1-s) : s;

        // ======== AB: scores + stale-max softmax + unnormalized ctx (128 tasks) =
        for(int task = dbid; task < 128; task += NSM){
            int b = task >> 3, tp = task & 7;
            int t0 = tp*64;
            int bg = hf*BH + b;
            #pragma unroll
            for(int q=0;q<2;q++){
                int n = htid + q*256;
                float a0=0.f;
                #pragma unroll
                for(int kc=0;kc<8;kc++)
                    a0 += g_decp[((kc*DOMS+dom)*BH + b)*HH + n];
                S.a.d0[n]=a0; S.a.vs[n]=v[n];
            }
            hbar(barid);
            #pragma unroll 1
            for(int i=0;i<8;i++){
                int tl = warp*8 + i;
                const __half* e = &g_ench[(long)(bg*TT + t0 + tl)*HH];
                float s0=0.f;
                #pragma unroll
                for(int j=0;j<2;j++){
                    int h0 = lane*8 + j*256;
                    uint4 ev4 = *(const uint4*)&e[h0];
                    const __half2* eh = (const __half2*)&ev4;
                    float4 d01 = *(const float4*)&S.a.d0[h0];
                    float4 d23 = *(const float4*)&S.a.d0[h0+4];
                    float4 v01 = *(const float4*)&S.a.vs[h0];
                    float4 v23 = *(const float4*)&S.a.vs[h0+4];
                    float2 e0 = __half22float2(eh[0]);
                    float2 e1 = __half22float2(eh[1]);
                    float2 e2 = __half22float2(eh[2]);
                    float2 e3 = __half22float2(eh[3]);
                    s0 += v01.x*fast_tanh(e0.x + d01.x) + v01.y*fast_tanh(e0.y + d01.y);
                    s0 += v01.z*fast_tanh(e1.x + d01.z) + v01.w*fast_tanh(e1.y + d01.w);
                    s0 += v23.x*fast_tanh(e2.x + d23.x) + v23.y*fast_tanh(e2.y + d23.y);
                    s0 += v23.z*fast_tanh(e3.x + d23.z) + v23.w*fast_tanh(e3.y + d23.w);
                }
                s0 = warpSum(s0);
                if(lane==0) S.a.sw0[tl] = s0;
            }
            hbar(barid);
            const float* mpr = g_mp + (s&1)*(8*DOMS*BH);
            float m0 = mpr[(0*DOMS+dom)*BH+b];
            #pragma unroll
            for(int p=1;p<8;p++) m0 = fmaxf(m0, mpr[(p*DOMS+dom)*BH+b]);
            if(htid < 64){
                float sc = S.a.sw0[htid];
                float e = __expf(sc - m0);
                S.a.sw0[htid] = e;
                float z = warpSum(e);
                float mx = warpMax(sc);
                if(lane==0){ S.a.red0[warp] = z; S.a.red1[warp] = mx; }
            }
            hbar(barid);
            if(htid == 0){
                g_zp[(tp*DOMS+dom)*BH+b] = S.a.red0[0] + S.a.red0[1];
                g_mp[((s+1)&1)*(8*DOMS*BH) + (tp*DOMS+dom)*BH+b] =
                    fmaxf(S.a.red1[0], S.a.red1[1]);
            }
            hbar(barid);
            const __half2* xb = (const __half2*)&g_xh[(long)(bg*TT + t0)*DD];
            #pragma unroll 1
            for(int q=0;q<2;q++){
                int idx = htid + q*256;
                if(idx < 384){
                    float ax=0.f, ay=0.f;
                    #pragma unroll 8
                    for(int t=0;t<64;t++){
                        float w = S.a.sw0[t];
                        float2 xv = __half22float2(xb[(long)t*384 + idx]);
                        ax += w*xv.x; ay += w*xv.y;
                    }
                    *(float2*)&g_ctxp[((tp*DOMS+dom)*BH + b)*DD + idx*2] = make_float2(ax, ay);
                }
            }
            hbar(barid);
        }
        gbarh(barid, ctr, bt, htid); bt += NSM;

        // ======== C: gates GEMM via fp16 mma, M=16 (128 tasks: nt16 x kc8) ======
        for(int task = dbid; task < 128; task += NSM){
            int nt = task & 15, kc = task >> 4;
            int n0 = nt*128, k0 = kc*256;
            if(htid < BH){
                float z=0.f;
                #pragma unroll
                for(int p=0;p<8;p++) z += g_zp[(p*DOMS+dom)*BH + htid];
                S.c.zinv[htid] = 1.0f/z;
            }
            hbar(barid);
            #pragma unroll
            for(int r=0;r<8;r++){
                int idx = htid + (r<<8);
                int b = idx>>7, kp = idx&127;
                int k = k0 + kp*2;
                __half2 hv;
                if(kc < 3){
                    float zi = S.c.zinv[b];
                    float sx=0.f, sy=0.f;
                    #pragma unroll
                    for(int p=0;p<8;p++){
                        float2 cp = *(const float2*)&g_ctxp[((p*DOMS+dom)*BH+b)*DD + k];
                        sx += cp.x; sy += cp.y;
                    }
                    hv = __floats2half2_rn(sx*zi, sy*zi);
                } else if(kc < 6){
                    int bg = hf*BH + b;
                    hv = *(const __half2*)&g_xh[(long)(bg*TT + t_cur)*DD + (k-768)];
                } else {
                    float2 h2 = *(const float2*)&g_h[(dom*BH+b)*HH + (k-1536)];
                    hv = __floats2half2_rn(h2.x, h2.y);
                }
                int ks = kp>>3, kkp = kp&7;
                int tq = kkp&3, khalf = kkp>>2;
                int gq = b&7, hi = b>>3;
                S.c.Ap[(ks*32 + gq*4 + tq)*4 + khalf*2 + hi] = *(uint32_t*)&hv;
            }
            hbar(barid);
            int nw = warp>>1, kh = warp&1;     // 4 n-warps x 2 k-halves
            float acc[4][4];
            #pragma unroll
            for(int j=0;j<4;j++)
                #pragma unroll
                for(int r=0;r<4;r++) acc[j][r]=0.f;
            const uint2* Bp = g_WcatPh + ((size_t)dir*128*256*32);
            #pragma unroll
            for(int i8=0;i8<8;i8++){
                int ksg = kh*8 + i8;
                uint4 A0 = *(const uint4*)&S.c.Ap[(ksg*32 + lane)*4];
                int k16g = kc*16 + ksg;
                #pragma unroll
                for(int j=0;j<4;j++){
                    int n8g = nt*16 + nw*4 + j;
                    uint2 bb2 = Bp[((size_t)k16g*256 + n8g)*32 + lane];
                    mma_f16(acc[j], (const uint32_t*)&A0, bb2.x, bb2.y);
                }
            }
            hbar(barid);
            float* buf = (float*)S.c.Ap;
            if(kh == 1){
                #pragma unroll
                for(int j=0;j<4;j++)
                    #pragma unroll
                    for(int r=0;r<4;r++)
                        buf[((nw*4+j)*4+r)*32 + lane] = acc[j][r];
            }
            hbar(barid);
            if(kh == 0){
                int gid = lane>>2, tg = lane&3;
                #pragma unroll
                for(int j=0;j<4;j++){
                    const float* b4 = &buf[((nw*4+j)*4)*32];
                    float c0 = acc[j][0] + b4[0*32 + lane];
                    float c1 = acc[j][1] + b4[1*32 + lane];
                    float c2 = acc[j][2] + b4[2*32 + lane];
                    float c3 = acc[j][3] + b4[3*32 + lane];
                    int n = n0 + (nw*4+j)*8 + tg*2;
                    *(float2*)&g_gpart[((long)(dom*8+kc)*BH + gid)*N4H + n]   = make_float2(c0,c1);
                    *(float2*)&g_gpart[((long)(dom*8+kc)*BH + gid+8)*N4H + n] = make_float2(c2,c3);
                }
            }
            hbar(barid);
        }
        gbarh(barid, ctr, bt, htid); bt += NSM;

        // ======== D: LSTM pointwise (grid-strided over domain) ==================
        for(int idx = dbid*256 + htid; idx < BH*HH; idx += NSM*256){
            int hc = idx & (HH-1);
            int b  = idx >> 9;
            float4 gs = make_float4(0.f,0.f,0.f,0.f);
            #pragma unroll
            for(int p=0;p<8;p++){
                float4 gp = *(const float4*)&g_gpart[((long)(dom*8+p)*BH + b)*N4H + hc*4];
                gs.x+=gp.x; gs.y+=gp.y; gs.z+=gp.z; gs.w+=gp.w;
            }
            float4 bc = *(const float4*)&g_bcat[dir*N4H + hc*4];
            float ig = sigm(gs.x+bc.x);
            float fg = sigm(gs.y+bc.y);
            float gg = tanh_acc(gs.z+bc.z);
            float og = sigm(gs.w+bc.w);
            int ix = (dom*BH+b)*HH + hc;
            float c = fg*g_c[ix] + ig*gg;
            float h = og*tanh_acc(c);
            g_c[ix]=c; g_h[ix]=h;
            g_hs[((long)(dir*TT + t_cur)*BB + hf*BH + b)*HH + hc] = h;
        }
        gbarh(barid, ctr, bt, htid); bt += NSM;

        // ======== E: dec partials (h @ WdecT), 128 tasks: nt16 x kc8 ============
        for(int task = dbid; task < 128; task += NSM){
            int nt = task & 15, kc = task >> 4;
            int n0 = nt*32, k0 = kc*64;
            #pragma unroll
            for(int r=0;r<4;r++){
                int lin = htid + 256*r;
                int bi = lin>>6, k = lin&63;
                S.e.Hs[bi][k] = g_h[(dom*BH+bi)*HH + k0 + k];
            }
            #pragma unroll
            for(int r=0;r<8;r++){
                int lin = htid + 256*r;
                int k = lin>>5, n = lin&31;
                S.e.Ws[k][n] = g_WdecT[(k0+k)*HH + n0 + n];
            }
            hbar(barid);
            int tb = htid>>4, tn = htid&15;
            float acc0=0.f, acc1=0.f;
            #pragma unroll 8
            for(int k=0;k<64;k++){
                float a = S.e.Hs[tb][k];
                float2 w2 = *(const float2*)&S.e.Ws[k][tn*2];
                acc0 += a*w2.x; acc1 += a*w2.y;
            }
            int n = n0 + tn*2;
            float bias0 = (kc==0) ? b_dec[n]   : 0.f;
            float bias1 = (kc==0) ? b_dec[n+1] : 0.f;
            g_decp[((kc*DOMS+dom)*BH + tb)*HH + n]   = acc0 + bias0;
            g_decp[((kc*DOMS+dom)*BH + tb)*HH + n+1] = acc1 + bias1;
            hbar(barid);
        }
        gbarh(barid, ctr, bt, htid); bt += NSM;
    }
}

// ---------------- final head ----------------
__global__ void k_head(const float* __restrict__ W_head, const float* __restrict__ b_head,
                       float* __restrict__ out){
    __shared__ float Ws[CC*2*HH];
    int tid = threadIdx.x;
    for(int i=tid;i<CC*2*HH;i+=256) Ws[i] = W_head[i];
    __syncthreads();
    int warp = tid>>5, lane = tid&31;
    int m = blockIdx.x*8 + warp;
    int b = m >> 9, t = m & (TT-1);
    const float* hfp = &g_hs[((long)(0*TT+t)*BB + b)*HH];
    const float* hbp = &g_hs[((long)(1*TT+t)*BB + b)*HH];
    float acc[CC];
    #pragma unroll
    for(int c=0;c<CC;c++) acc[c]=0.f;
    #pragma unroll 4
    for(int i=0;i<16;i++){
        int k = lane + i*32;
        float vf = hfp[k];
        float vb = hbp[k];
        #pragma unroll
        for(int c=0;c<CC;c++){
            acc[c] += vf*Ws[c*1024 + k] + vb*Ws[c*1024 + 512 + k];
        }
    }
    float res = 0.f;
    #pragma unroll
    for(int c=0;c<CC;c++){
        float r = warpSum(acc[c]);
        if(lane==c) res = r;
    }
    if(lane < CC) out[m*CC + lane] = res + b_head[lane];
}

// ---------------- launch ----------------
extern "C" void kernel_launch(void* const* d_in, const int* in_sizes, int n_in,
                              void* d_out, int out_size){
    const float* x      = (const float*)d_in[0];
    const float* Wf_ih  = (const float*)d_in[1];
    const float* Wf_hh  = (const float*)d_in[2];
    const float* bf     = (const float*)d_in[3];
    const float* Wb_ih  = (const float*)d_in[4];
    const float* Wb_hh  = (const float*)d_in[5];
    const float* bb     = (const float*)d_in[6];
    const float* W_enc  = (const float*)d_in[7];
    const float* b_enc  = (const float*)d_in[8];
    const float* W_dec  = (const float*)d_in[9];
    const float* b_dec  = (const float*)d_in[10];
    const float* v      = (const float*)d_in[11];
    const float* W_head = (const float*)d_in[12];
    const float* b_head = (const float*)d_in[13];
    float* out = (float*)d_out;

    int dev = 0;
    cudaGetDevice(&dev);
    int nsm = 128;
    cudaDeviceGetAttribute(&nsm, cudaDevAttrMultiProcessorCount, dev);

    k_init<<<1024, 256>>>(b_dec);
    k_prep<<<2048, 256>>>(Wf_ih, Wf_hh, bf, Wb_ih, Wb_hh, bb, W_dec, x);
    k_enc_gemm<<<dim3(8, 256), 256>>>(x, W_enc, b_enc);
    k_persist<<<2*nsm, 512>>>(x, v, b_dec, nsm);
    k_head<<<2048, 256>>>(W_head, b_head, out);
}